// round 2
// baseline (speedup 1.0000x reference)
#include <cuda_runtime.h>
#include <math.h>

#define N_NODES 200000
#define N_EDGES 3200000
#define HID 64
#define IN_CH 32
#define OUT_CH 16
#define NGRAPH 64

// ---------------- scratch (static __device__, no allocations) ----------------
__device__ float g_h[N_NODES * HID];     // node features (running)
__device__ float g_xs[N_NODES * HID];    // (h @ W^T) * dis[n]
__device__ float g_deg[N_NODES];
__device__ float g_dis[N_NODES];
__device__ int   g_cnt[N_NODES];         // in-degree (edges only)
__device__ int   g_ptr[N_NODES];         // CSR row start (exclusive prefix)
__device__ int   g_cur[N_NODES];         // scatter cursors
__device__ int2  g_epack[N_EDGES];       // CSR slot: {src, float_bits(w)}
__device__ float g_psum[NGRAPH * HID];
__device__ int   g_pcnt[NGRAPH];

__device__ __forceinline__ float gelu_exact(float v) {
    return 0.5f * v * (1.0f + erff(v * 0.70710678118654752f));
}

// ---------------- init ----------------
__global__ void k_init() {
    int i = blockIdx.x * blockDim.x + threadIdx.x;
    if (i < N_NODES) { g_deg[i] = 1.0f; g_cnt[i] = 0; }   // self-loop weight 1
    if (i < NGRAPH * HID) g_psum[i] = 0.0f;
    if (i < NGRAPH) g_pcnt[i] = 0;
}

// ---------------- degree + in-degree histogram ----------------
__global__ void k_deg(const int* __restrict__ dst, const float* __restrict__ ew) {
    int e = blockIdx.x * blockDim.x + threadIdx.x;
    if (e < N_EDGES) {
        int d = dst[e];
        atomicAdd(&g_deg[d], ew[e]);
        atomicAdd(&g_cnt[d], 1);
    }
}

// ---------------- single-block exclusive scan over g_cnt ----------------
__global__ void k_scan() {
    __shared__ int s[1024];
    const int C = (N_NODES + 1023) / 1024;  // 196
    int t = threadIdx.x;
    int base = t * C;
    int sum = 0;
    for (int i = 0; i < C; ++i) {
        int idx = base + i;
        if (idx < N_NODES) sum += g_cnt[idx];
    }
    s[t] = sum;
    __syncthreads();
    for (int off = 1; off < 1024; off <<= 1) {
        int v = (t >= off) ? s[t - off] : 0;
        __syncthreads();
        s[t] += v;
        __syncthreads();
    }
    int run = (t == 0) ? 0 : s[t - 1];
    for (int i = 0; i < C; ++i) {
        int idx = base + i;
        if (idx < N_NODES) {
            g_ptr[idx] = run;
            g_cur[idx] = run;
            run += g_cnt[idx];
        }
    }
}

__global__ void k_dis() {
    int i = blockIdx.x * blockDim.x + threadIdx.x;
    if (i < N_NODES) g_dis[i] = rsqrtf(g_deg[i]);  // deg >= 1 always (self loop)
}

// ---------------- scatter edges into CSR (packed 8B records) ----------------
__global__ void k_scatter(const int* __restrict__ src, const int* __restrict__ dst,
                          const float* __restrict__ ew) {
    int e = blockIdx.x * blockDim.x + threadIdx.x;
    if (e < N_EDGES) {
        int p = atomicAdd(&g_cur[dst[e]], 1);
        g_epack[p] = make_int2(src[e], __float_as_int(ew[e]));
    }
}

// ---------------- proj: h = gelu(x @ Wp^T + bp), 16 nodes / block ----------------
__global__ void k_proj(const float* __restrict__ x, const float* __restrict__ W,
                       const float* __restrict__ b) {
    __shared__ float ws[64 * 33];       // pad 33 -> conflict-free
    __shared__ float4 hs[16 * 8];       // 16 nodes x 32 floats
    int tid = threadIdx.x;
    for (int idx = tid; idx < 64 * 32; idx += 256) {
        int j = idx >> 5, k = idx & 31;
        ws[j * 33 + k] = W[idx];
    }
    int n0 = blockIdx.x * 16;
    const float4* xsrc = (const float4*)(x + (size_t)n0 * IN_CH);
    for (int idx = tid; idx < 128; idx += 256) hs[idx] = xsrc[idx];
    __syncthreads();

    int j = tid & 63, q = tid >> 6;
    float a0 = 0.f, a1 = 0.f, a2 = 0.f, a3 = 0.f;
#pragma unroll
    for (int k4 = 0; k4 < 8; ++k4) {
        float4 h0 = hs[q * 8 + k4];
        float4 h1 = hs[(q + 4) * 8 + k4];
        float4 h2 = hs[(q + 8) * 8 + k4];
        float4 h3 = hs[(q + 12) * 8 + k4];
        float w0 = ws[j * 33 + 4 * k4 + 0];
        float w1 = ws[j * 33 + 4 * k4 + 1];
        float w2 = ws[j * 33 + 4 * k4 + 2];
        float w3 = ws[j * 33 + 4 * k4 + 3];
        a0 += h0.x * w0 + h0.y * w1 + h0.z * w2 + h0.w * w3;
        a1 += h1.x * w0 + h1.y * w1 + h1.z * w2 + h1.w * w3;
        a2 += h2.x * w0 + h2.y * w1 + h2.z * w2 + h2.w * w3;
        a3 += h3.x * w0 + h3.y * w1 + h3.z * w2 + h3.w * w3;
    }
    float bb = b[j];
    g_h[(size_t)(n0 + q) * HID + j]      = gelu_exact(a0 + bb);
    g_h[(size_t)(n0 + q + 4) * HID + j]  = gelu_exact(a1 + bb);
    g_h[(size_t)(n0 + q + 8) * HID + j]  = gelu_exact(a2 + bb);
    g_h[(size_t)(n0 + q + 12) * HID + j] = gelu_exact(a3 + bb);
}

// ---------------- lin: xs = (h @ W^T) * dis, 16 nodes / block ----------------
__global__ void k_lin(const float* __restrict__ W) {
    __shared__ float ws[64 * 65];       // pad 65 -> conflict-free
    __shared__ float4 hs[16 * 16];      // 16 nodes x 64 floats
    int tid = threadIdx.x;
    for (int idx = tid; idx < 4096; idx += 256) {
        int j = idx >> 6, k = idx & 63;
        ws[j * 65 + k] = W[idx];
    }
    int n0 = blockIdx.x * 16;
    const float4* hsrc = (const float4*)(g_h + (size_t)n0 * HID);
    for (int idx = tid; idx < 256; idx += 256) hs[idx] = hsrc[idx];
    __syncthreads();

    int j = tid & 63, q = tid >> 6;
    float a0 = 0.f, a1 = 0.f, a2 = 0.f, a3 = 0.f;
#pragma unroll
    for (int k4 = 0; k4 < 16; ++k4) {
        float4 h0 = hs[q * 16 + k4];
        float4 h1 = hs[(q + 4) * 16 + k4];
        float4 h2 = hs[(q + 8) * 16 + k4];
        float4 h3 = hs[(q + 12) * 16 + k4];
        float w0 = ws[j * 65 + 4 * k4 + 0];
        float w1 = ws[j * 65 + 4 * k4 + 1];
        float w2 = ws[j * 65 + 4 * k4 + 2];
        float w3 = ws[j * 65 + 4 * k4 + 3];
        a0 += h0.x * w0 + h0.y * w1 + h0.z * w2 + h0.w * w3;
        a1 += h1.x * w0 + h1.y * w1 + h1.z * w2 + h1.w * w3;
        a2 += h2.x * w0 + h2.y * w1 + h2.z * w2 + h2.w * w3;
        a3 += h3.x * w0 + h3.y * w1 + h3.z * w2 + h3.w * w3;
    }
    int n;
    n = n0 + q;      g_xs[(size_t)n * HID + j] = a0 * g_dis[n];
    n = n0 + q + 4;  g_xs[(size_t)n * HID + j] = a1 * g_dis[n];
    n = n0 + q + 8;  g_xs[(size_t)n * HID + j] = a2 * g_dis[n];
    n = n0 + q + 12; g_xs[(size_t)n * HID + j] = a3 * g_dis[n];
}

// ---------------- fused: aggregate + bias + gelu + LN + residual ----------------
// one warp per node, lane holds channels {2l, 2l+1}.
// edge metadata: each lane loads a distinct packed record, broadcast via shfl.
__global__ void k_agg(const float* __restrict__ bias, const float* __restrict__ gam,
                      const float* __restrict__ bet) {
    int n = (blockIdx.x * blockDim.x + threadIdx.x) >> 5;
    int lane = threadIdx.x & 31;
    if (n >= N_NODES) return;

    // self term: xs[n] already contains dis[n]; final *dis[n] gives dis^2
    float2 acc = *(const float2*)&g_xs[(size_t)n * HID + 2 * lane];
    int beg = g_ptr[n];
    int cnt = g_cnt[n];

    for (int base = 0; base < cnt; base += 32) {
        int m = min(32, cnt - base);
        int2 my = make_int2(0, 0);
        if (lane < m) my = __ldg(&g_epack[beg + base + lane]);
        for (int k = 0; k < m; ++k) {
            int si = __shfl_sync(0xffffffffu, my.x, k);
            float wi = __int_as_float(__shfl_sync(0xffffffffu, my.y, k));
            float2 v = *(const float2*)&g_xs[(size_t)si * HID + 2 * lane];
            acc.x += v.x * wi;
            acc.y += v.y * wi;
        }
    }

    float dn = g_dis[n];
    float gl0 = gelu_exact(acc.x * dn + bias[2 * lane]);
    float gl1 = gelu_exact(acc.y * dn + bias[2 * lane + 1]);

    // LayerNorm over 64 channels via warp reductions
    float s = gl0 + gl1;
#pragma unroll
    for (int o = 16; o; o >>= 1) s += __shfl_xor_sync(0xffffffffu, s, o);
    float mu = s * (1.0f / 64.0f);
    float d0 = gl0 - mu, d1 = gl1 - mu;
    float sq = d0 * d0 + d1 * d1;
#pragma unroll
    for (int o = 16; o; o >>= 1) sq += __shfl_xor_sync(0xffffffffu, sq, o);
    float rs = rsqrtf(sq * (1.0f / 64.0f) + 1e-5f);
    float v0 = d0 * rs * gam[2 * lane] + bet[2 * lane];
    float v1 = d1 * rs * gam[2 * lane + 1] + bet[2 * lane + 1];

    float2 hv = *(float2*)&g_h[(size_t)n * HID + 2 * lane];
    hv.x += v0;
    hv.y += v1;
    *(float2*)&g_h[(size_t)n * HID + 2 * lane] = hv;
}

// ---------------- pooling: run-length accumulate over sorted batch ----------------
__global__ void k_pool(const int* __restrict__ batch) {
    int j = threadIdx.x;            // 0..63 channel
    int ty = threadIdx.y;           // 0..3 interleave
    int n0 = blockIdx.x * 2048;
    int nend = min(n0 + 2048, N_NODES);
    float acc = 0.f;
    int curg = -1;
    for (int n = n0 + ty; n < nend; n += 4) {
        int g = batch[n];
        if (g != curg) {
            if (curg >= 0) atomicAdd(&g_psum[curg * HID + j], acc);
            acc = 0.f;
            curg = g;
        }
        acc += g_h[(size_t)n * HID + j];
    }
    if (curg >= 0) atomicAdd(&g_psum[curg * HID + j], acc);
}

__global__ void k_count(const int* __restrict__ batch) {
    __shared__ int hist[NGRAPH];
    int tid = threadIdx.x;
    if (tid < NGRAPH) hist[tid] = 0;
    __syncthreads();
    int n0 = blockIdx.x * 2048;
    int nend = min(n0 + 2048, N_NODES);
    for (int n = n0 + tid; n < nend; n += 256) atomicAdd(&hist[batch[n]], 1);
    __syncthreads();
    if (tid < NGRAPH && hist[tid]) atomicAdd(&g_pcnt[tid], hist[tid]);
}

// ---------------- head: out = (psum/cnt) @ pool_w^T + pool_b ----------------
__global__ void k_head(const float* __restrict__ pw, const float* __restrict__ pb,
                       float* __restrict__ out) {
    int tid = threadIdx.x;          // 1024 = 64 graphs * 16 outs
    int g = tid >> 4, o = tid & 15;
    float inv = 1.0f / fmaxf((float)g_pcnt[g], 1.0f);
    float acc = 0.f;
#pragma unroll
    for (int jj = 0; jj < HID; ++jj) acc += g_psum[g * HID + jj] * pw[o * HID + jj];
    out[g * OUT_CH + o] = acc * inv + pb[o];
}

// ---------------- launch ----------------
extern "C" void kernel_launch(void* const* d_in, const int* in_sizes, int n_in,
                              void* d_out, int out_size) {
    const float* x      = (const float*)d_in[0];
    const float* ew     = (const float*)d_in[1];
    const float* proj_w = (const float*)d_in[2];
    const float* proj_b = (const float*)d_in[3];
    const float* w1     = (const float*)d_in[4];
    const float* b1     = (const float*)d_in[5];
    const float* w2     = (const float*)d_in[6];
    const float* b2     = (const float*)d_in[7];
    const float* ln1g   = (const float*)d_in[8];
    const float* ln1b   = (const float*)d_in[9];
    const float* ln2g   = (const float*)d_in[10];
    const float* ln2b   = (const float*)d_in[11];
    const float* pw     = (const float*)d_in[12];
    const float* pb     = (const float*)d_in[13];
    const int*   src    = (const int*)d_in[14];
    const int*   dst    = (const int*)d_in[15];
    const int*   batch  = (const int*)d_in[16];
    float* out = (float*)d_out;

    k_init<<<(N_NODES + 255) / 256, 256>>>();
    k_deg<<<(N_EDGES + 255) / 256, 256>>>(dst, ew);
    k_scan<<<1, 1024>>>();
    k_dis<<<(N_NODES + 255) / 256, 256>>>();
    k_scatter<<<(N_EDGES + 255) / 256, 256>>>(src, dst, ew);

    k_proj<<<N_NODES / 16, 256>>>(x, proj_w, proj_b);

    k_lin<<<N_NODES / 16, 256>>>(w1);
    k_agg<<<N_NODES / 8, 256>>>(b1, ln1g, ln1b);

    k_lin<<<N_NODES / 16, 256>>>(w2);
    k_agg<<<N_NODES / 8, 256>>>(b2, ln2g, ln2b);

    k_pool<<<(N_NODES + 2047) / 2048, dim3(64, 4)>>>(batch);
    k_count<<<(N_NODES + 2047) / 2048, 256>>>(batch);
    k_head<<<1, 1024>>>(pw, pb, out);
}

// round 5
// speedup vs baseline: 1.0567x; 1.0567x over previous
#include <cuda_runtime.h>
#include <math.h>

#define N_NODES 200000
#define N_EDGES 3200000
#define HID 64
#define IN_CH 32
#define OUT_CH 16
#define NGRAPH 64
#define FULLM 0xffffffffu

// ---------------- scratch (static __device__, no allocations) ----------------
__device__ float g_h[N_NODES * HID];     // node features (running)
__device__ float g_xs[N_NODES * HID];    // (h @ W^T) * dis[n]
__device__ float g_dis[N_NODES];
__device__ int   g_cnt[N_NODES];         // in-degree (edges only)
__device__ int   g_ptr[N_NODES];         // CSR row start (exclusive prefix)
__device__ int   g_cur[N_NODES];         // scatter cursors
__device__ int2  g_epack[N_EDGES];       // CSR slot: {src, float_bits(w)}
__device__ float g_psum[NGRAPH * HID];
__device__ int   g_pcnt[NGRAPH];

__device__ __forceinline__ float gelu_exact(float v) {
    return 0.5f * v * (1.0f + erff(v * 0.70710678118654752f));
}

// ---------------- init ----------------
__global__ void k_init() {
    int i = blockIdx.x * blockDim.x + threadIdx.x;
    if (i < N_NODES) g_cnt[i] = 0;
    if (i < NGRAPH * HID) g_psum[i] = 0.0f;
    if (i < NGRAPH) g_pcnt[i] = 0;
}

// ---------------- in-degree histogram (int RED only, 4 edges/thread) --------
__global__ void k_cnt(const int* __restrict__ dst) {
    int t = blockIdx.x * blockDim.x + threadIdx.x;
    if (t < N_EDGES / 4) {
        int4 d = __ldg((const int4*)dst + t);
        atomicAdd(&g_cnt[d.x], 1);
        atomicAdd(&g_cnt[d.y], 1);
        atomicAdd(&g_cnt[d.z], 1);
        atomicAdd(&g_cnt[d.w], 1);
    }
}

// ---------------- single-block exclusive scan over g_cnt ----------------
__global__ void k_scan() {
    __shared__ int s[1024];
    const int C = (N_NODES + 1023) / 1024;  // 196
    int t = threadIdx.x;
    int base = t * C;
    int sum = 0;
    for (int i = 0; i < C; ++i) {
        int idx = base + i;
        if (idx < N_NODES) sum += g_cnt[idx];
    }
    s[t] = sum;
    __syncthreads();
    for (int off = 1; off < 1024; off <<= 1) {
        int v = (t >= off) ? s[t - off] : 0;
        __syncthreads();
        s[t] += v;
        __syncthreads();
    }
    int run = (t == 0) ? 0 : s[t - 1];
    for (int i = 0; i < C; ++i) {
        int idx = base + i;
        if (idx < N_NODES) {
            g_ptr[idx] = run;
            g_cur[idx] = run;
            run += g_cnt[idx];
        }
    }
}

// ---------------- scatter edges into CSR (packed 8B records, 4 edges/thread) -
__global__ void k_scatter(const int* __restrict__ src, const int* __restrict__ dst,
                          const float* __restrict__ ew) {
    int t = blockIdx.x * blockDim.x + threadIdx.x;
    if (t < N_EDGES / 4) {
        int4 s4 = __ldg((const int4*)src + t);
        int4 d4 = __ldg((const int4*)dst + t);
        float4 w4 = __ldg((const float4*)ew + t);
        int p;
        p = atomicAdd(&g_cur[d4.x], 1); g_epack[p] = make_int2(s4.x, __float_as_int(w4.x));
        p = atomicAdd(&g_cur[d4.y], 1); g_epack[p] = make_int2(s4.y, __float_as_int(w4.y));
        p = atomicAdd(&g_cur[d4.z], 1); g_epack[p] = make_int2(s4.z, __float_as_int(w4.z));
        p = atomicAdd(&g_cur[d4.w], 1); g_epack[p] = make_int2(s4.w, __float_as_int(w4.w));
    }
}

// ---------------- deg+dis from CSR: warp per node, contiguous reads ----------
__global__ void k_degdis() {
    int n = (blockIdx.x * blockDim.x + threadIdx.x) >> 5;
    int lane = threadIdx.x & 31;
    if (n >= N_NODES) return;
    int beg = g_ptr[n], cnt = g_cnt[n];
    float s = 0.f;
    for (int e = beg + lane; e < beg + cnt; e += 32)
        s += __int_as_float(__ldg(&g_epack[e].y));
#pragma unroll
    for (int o = 16; o; o >>= 1) s += __shfl_xor_sync(FULLM, s, o);
    if (lane == 0) g_dis[n] = rsqrtf(1.0f + s);   // +1 = self-loop weight
}

// ---------------- proj: h = gelu(x @ Wp^T + bp), 16 nodes / block ----------------
__global__ void __launch_bounds__(256) k_proj(const float* __restrict__ x,
                                              const float* __restrict__ W,
                                              const float* __restrict__ b) {
    __shared__ float ws[64 * 33];       // pad 33 -> conflict-free
    __shared__ float4 hs[16 * 8];       // 16 nodes x 32 floats
    int tid = threadIdx.x;
    for (int idx = tid; idx < 64 * 32; idx += 256) {
        int j = idx >> 5, k = idx & 31;
        ws[j * 33 + k] = W[idx];
    }
    int n0 = blockIdx.x * 16;
    const float4* xsrc = (const float4*)(x + (size_t)n0 * IN_CH);
    for (int idx = tid; idx < 128; idx += 256) hs[idx] = xsrc[idx];
    __syncthreads();

    int j = tid & 63, q = tid >> 6;
    float a0 = 0.f, a1 = 0.f, a2 = 0.f, a3 = 0.f;
#pragma unroll
    for (int k4 = 0; k4 < 8; ++k4) {
        float4 h0 = hs[q * 8 + k4];
        float4 h1 = hs[(q + 4) * 8 + k4];
        float4 h2 = hs[(q + 8) * 8 + k4];
        float4 h3 = hs[(q + 12) * 8 + k4];
        float w0 = ws[j * 33 + 4 * k4 + 0];
        float w1 = ws[j * 33 + 4 * k4 + 1];
        float w2 = ws[j * 33 + 4 * k4 + 2];
        float w3 = ws[j * 33 + 4 * k4 + 3];
        a0 += h0.x * w0 + h0.y * w1 + h0.z * w2 + h0.w * w3;
        a1 += h1.x * w0 + h1.y * w1 + h1.z * w2 + h1.w * w3;
        a2 += h2.x * w0 + h2.y * w1 + h2.z * w2 + h2.w * w3;
        a3 += h3.x * w0 + h3.y * w1 + h3.z * w2 + h3.w * w3;
    }
    float bb = b[j];
    g_h[(size_t)(n0 + q) * HID + j]      = gelu_exact(a0 + bb);
    g_h[(size_t)(n0 + q + 4) * HID + j]  = gelu_exact(a1 + bb);
    g_h[(size_t)(n0 + q + 8) * HID + j]  = gelu_exact(a2 + bb);
    g_h[(size_t)(n0 + q + 12) * HID + j] = gelu_exact(a3 + bb);
}

// ---------------- lin: xs = (h @ W^T) * dis, 16 nodes / block ----------------
__global__ void __launch_bounds__(256) k_lin(const float* __restrict__ W) {
    __shared__ float ws[64 * 65];       // pad 65 -> conflict-free
    __shared__ float4 hs[16 * 16];      // 16 nodes x 64 floats
    int tid = threadIdx.x;
    for (int idx = tid; idx < 4096; idx += 256) {
        int j = idx >> 6, k = idx & 63;
        ws[j * 65 + k] = W[idx];
    }
    int n0 = blockIdx.x * 16;
    const float4* hsrc = (const float4*)(g_h + (size_t)n0 * HID);
    for (int idx = tid; idx < 256; idx += 256) hs[idx] = hsrc[idx];
    __syncthreads();

    int j = tid & 63, q = tid >> 6;
    float a0 = 0.f, a1 = 0.f, a2 = 0.f, a3 = 0.f;
#pragma unroll
    for (int k4 = 0; k4 < 16; ++k4) {
        float4 h0 = hs[q * 16 + k4];
        float4 h1 = hs[(q + 4) * 16 + k4];
        float4 h2 = hs[(q + 8) * 16 + k4];
        float4 h3 = hs[(q + 12) * 16 + k4];
        float w0 = ws[j * 65 + 4 * k4 + 0];
        float w1 = ws[j * 65 + 4 * k4 + 1];
        float w2 = ws[j * 65 + 4 * k4 + 2];
        float w3 = ws[j * 65 + 4 * k4 + 3];
        a0 += h0.x * w0 + h0.y * w1 + h0.z * w2 + h0.w * w3;
        a1 += h1.x * w0 + h1.y * w1 + h1.z * w2 + h1.w * w3;
        a2 += h2.x * w0 + h2.y * w1 + h2.z * w2 + h2.w * w3;
        a3 += h3.x * w0 + h3.y * w1 + h3.z * w2 + h3.w * w3;
    }
    int n;
    n = n0 + q;      g_xs[(size_t)n * HID + j] = a0 * g_dis[n];
    n = n0 + q + 4;  g_xs[(size_t)n * HID + j] = a1 * g_dis[n];
    n = n0 + q + 8;  g_xs[(size_t)n * HID + j] = a2 * g_dis[n];
    n = n0 + q + 12; g_xs[(size_t)n * HID + j] = a3 * g_dis[n];
}

// ---------------- fused: aggregate + bias + gelu + LN + residual ----------------
// one warp per node; lane l owns channels 4*(l&15)..+3 (float4), half = l>>4
// processes edge 2k+half; two edges per iteration, one LDG.128 per lane.
__global__ void __launch_bounds__(256) k_agg(const float* __restrict__ bias,
                                             const float* __restrict__ gam,
                                             const float* __restrict__ bet) {
    int n = (blockIdx.x * blockDim.x + threadIdx.x) >> 5;
    int lane = threadIdx.x & 31;
    if (n >= N_NODES) return;
    int c = lane & 15;        // float4 channel group
    int half = lane >> 4;

    // self term only in half 0 (halves are summed at the end)
    float4 acc = make_float4(0.f, 0.f, 0.f, 0.f);
    if (half == 0) acc = *(const float4*)&g_xs[(size_t)n * HID + 4 * c];

    int beg = g_ptr[n];
    int cnt = g_cnt[n];
    for (int base = 0; base < cnt; base += 32) {
        int m = min(32, cnt - base);
        int2 my = make_int2(n, 0);                     // pad: row n, weight 0
        if (lane < m) my = __ldg(&g_epack[beg + base + lane]);
        int iters = (m + 1) >> 1;
        for (int k = 0; k < iters; ++k) {
            int idx = 2 * k + half;
            int si = __shfl_sync(FULLM, my.x, idx);
            float wi = __int_as_float(__shfl_sync(FULLM, my.y, idx));
            float4 v = __ldg((const float4*)&g_xs[(size_t)si * HID + 4 * c]);
            acc.x += v.x * wi;
            acc.y += v.y * wi;
            acc.z += v.z * wi;
            acc.w += v.w * wi;
        }
    }
    // merge halves (after this both halves hold identical full sums)
    acc.x += __shfl_xor_sync(FULLM, acc.x, 16);
    acc.y += __shfl_xor_sync(FULLM, acc.y, 16);
    acc.z += __shfl_xor_sync(FULLM, acc.z, 16);
    acc.w += __shfl_xor_sync(FULLM, acc.w, 16);

    float dn = g_dis[n];
    float4 bb = ((const float4*)bias)[c];
    float g0 = gelu_exact(acc.x * dn + bb.x);
    float g1 = gelu_exact(acc.y * dn + bb.y);
    float g2 = gelu_exact(acc.z * dn + bb.z);
    float g3 = gelu_exact(acc.w * dn + bb.w);

    // LayerNorm over 64 channels: reduce across the 16-lane group (halves identical)
    float s = g0 + g1 + g2 + g3;
#pragma unroll
    for (int o = 8; o; o >>= 1) s += __shfl_xor_sync(FULLM, s, o);
    float mu = s * (1.0f / 64.0f);
    float d0 = g0 - mu, d1 = g1 - mu, d2 = g2 - mu, d3 = g3 - mu;
    float sq = d0 * d0 + d1 * d1 + d2 * d2 + d3 * d3;
#pragma unroll
    for (int o = 8; o; o >>= 1) sq += __shfl_xor_sync(FULLM, sq, o);
    float rs = rsqrtf(sq * (1.0f / 64.0f) + 1e-5f);

    if (half == 0) {
        float4 gm = ((const float4*)gam)[c];
        float4 bt = ((const float4*)bet)[c];
        float4* hp = (float4*)&g_h[(size_t)n * HID + 4 * c];
        float4 hv = *hp;
        hv.x += d0 * rs * gm.x + bt.x;
        hv.y += d1 * rs * gm.y + bt.y;
        hv.z += d2 * rs * gm.z + bt.z;
        hv.w += d3 * rs * gm.w + bt.w;
        *hp = hv;
    }
}

// ---------------- pooling: run-length accumulate over sorted batch ----------------
__global__ void k_pool(const int* __restrict__ batch) {
    int j = threadIdx.x;            // 0..63 channel
    int ty = threadIdx.y;           // 0..3 interleave
    int n0 = blockIdx.x * 2048;
    int nend = min(n0 + 2048, N_NODES);
    float acc = 0.f;
    int curg = -1;
    for (int n = n0 + ty; n < nend; n += 4) {
        int g = batch[n];
        if (g != curg) {
            if (curg >= 0) atomicAdd(&g_psum[curg * HID + j], acc);
            acc = 0.f;
            curg = g;
        }
        acc += g_h[(size_t)n * HID + j];
    }
    if (curg >= 0) atomicAdd(&g_psum[curg * HID + j], acc);
}

__global__ void k_count(const int* __restrict__ batch) {
    __shared__ int hist[NGRAPH];
    int tid = threadIdx.x;
    if (tid < NGRAPH) hist[tid] = 0;
    __syncthreads();
    int n0 = blockIdx.x * 2048;
    int nend = min(n0 + 2048, N_NODES);
    for (int n = n0 + tid; n < nend; n += 256) atomicAdd(&hist[batch[n]], 1);
    __syncthreads();
    if (tid < NGRAPH && hist[tid]) atomicAdd(&g_pcnt[tid], hist[tid]);
}

// ---------------- head: out = (psum/cnt) @ pool_w^T + pool_b ----------------
__global__ void k_head(const float* __restrict__ pw, const float* __restrict__ pb,
                       float* __restrict__ out) {
    int tid = threadIdx.x;          // 1024 = 64 graphs * 16 outs
    int g = tid >> 4, o = tid & 15;
    float inv = 1.0f / fmaxf((float)g_pcnt[g], 1.0f);
    float acc = 0.f;
#pragma unroll
    for (int jj = 0; jj < HID; ++jj) acc += g_psum[g * HID + jj] * pw[o * HID + jj];
    out[g * OUT_CH + o] = acc * inv + pb[o];
}

// ---------------- launch ----------------
extern "C" void kernel_launch(void* const* d_in, const int* in_sizes, int n_in,
                              void* d_out, int out_size) {
    const float* x      = (const float*)d_in[0];
    const float* ew     = (const float*)d_in[1];
    const float* proj_w = (const float*)d_in[2];
    const float* proj_b = (const float*)d_in[3];
    const float* w1     = (const float*)d_in[4];
    const float* b1     = (const float*)d_in[5];
    const float* w2     = (const float*)d_in[6];
    const float* b2     = (const float*)d_in[7];
    const float* ln1g   = (const float*)d_in[8];
    const float* ln1b   = (const float*)d_in[9];
    const float* ln2g   = (const float*)d_in[10];
    const float* ln2b   = (const float*)d_in[11];
    const float* pw     = (const float*)d_in[12];
    const float* pb     = (const float*)d_in[13];
    const int*   src    = (const int*)d_in[14];
    const int*   dst    = (const int*)d_in[15];
    const int*   batch  = (const int*)d_in[16];
    float* out = (float*)d_out;

    k_init<<<(N_NODES + 255) / 256, 256>>>();
    k_cnt<<<(N_EDGES / 4 + 255) / 256, 256>>>(dst);
    k_scan<<<1, 1024>>>();
    k_scatter<<<(N_EDGES / 4 + 255) / 256, 256>>>(src, dst, ew);
    k_degdis<<<(N_NODES * 32 + 255) / 256, 256>>>();

    k_proj<<<N_NODES / 16, 256>>>(x, proj_w, proj_b);

    k_lin<<<N_NODES / 16, 256>>>(w1);
    k_agg<<<(N_NODES * 32 + 255) / 256, 256>>>(b1, ln1g, ln1b);

    k_lin<<<N_NODES / 16, 256>>>(w2);
    k_agg<<<(N_NODES * 32 + 255) / 256, 256>>>(b2, ln2g, ln2b);

    k_pool<<<(N_NODES + 2047) / 2048, dim3(64, 4)>>>(batch);
    k_count<<<(N_NODES + 2047) / 2048, 256>>>(batch);
    k_head<<<1, 1024>>>(pw, pb, out);
}